// round 3
// baseline (speedup 1.0000x reference)
#include <cuda_runtime.h>

#define N_NODES 50000
#define N_EDGES 600000
#define B_GR    4096
#define DIM     128
#define L_IT    3
#define EPSBN   1e-5f

// ---------------- device scratch (static globals: allocation-free) -------------
__device__ int   g_deg[2 * N_NODES];
__device__ int   g_offs[2 * (N_NODES + 1)];
__device__ int   g_cursor[2 * N_NODES];
__device__ int   g_csr[2 * N_EDGES];
__device__ float g_agg[2][N_NODES * DIM];
__device__ float g_xbuf[2][2][N_NODES * DIM];   // [pingpong][graph]
__device__ float g_pool[2][B_GR * DIM];

// ---------------- zero deg + pool ------------------------------------------------
__global__ void zero_kernel() {
    int i = blockIdx.x * blockDim.x + threadIdx.x;
    int stride = gridDim.x * blockDim.x;
    for (int j = i; j < 2 * N_NODES; j += stride) g_deg[j] = 0;
    float* p = &g_pool[0][0];
    for (int j = i; j < 2 * B_GR * DIM; j += stride) p[j] = 0.0f;
}

// ---------------- histogram of in-degrees ---------------------------------------
__global__ void hist_kernel(const int* __restrict__ e1, const int* __restrict__ e2) {
    int g = blockIdx.y;
    const int* dst = (g ? e2 : e1) + N_EDGES;
    int i = blockIdx.x * blockDim.x + threadIdx.x;
    if (i < N_EDGES) atomicAdd(&g_deg[g * N_NODES + dst[i]], 1);
}

// ---------------- single-block exclusive scan per graph -------------------------
__global__ void scan_kernel() {
    int g = blockIdx.x;
    const int* deg = g_deg + g * N_NODES;
    int* offs = g_offs + g * (N_NODES + 1);
    __shared__ int warpsum[32];
    __shared__ int s_running;
    __shared__ int s_chunk;
    if (threadIdx.x == 0) s_running = 0;
    __syncthreads();
    int lane = threadIdx.x & 31, w = threadIdx.x >> 5;
    for (int base = 0; base < N_NODES; base += 1024) {
        int i = base + threadIdx.x;
        int v = (i < N_NODES) ? deg[i] : 0;
        int s = v;
        #pragma unroll
        for (int o = 1; o < 32; o <<= 1) {
            int t = __shfl_up_sync(0xffffffffu, s, o);
            if (lane >= o) s += t;
        }
        if (lane == 31) warpsum[w] = s;
        __syncthreads();
        if (w == 0) {
            int ws = warpsum[lane];
            int ss = ws;
            #pragma unroll
            for (int o = 1; o < 32; o <<= 1) {
                int t = __shfl_up_sync(0xffffffffu, ss, o);
                if (lane >= o) ss += t;
            }
            if (lane == 31) s_chunk = ss;
            warpsum[lane] = ss - ws;   // exclusive warp offset
        }
        __syncthreads();
        int excl = s_running + warpsum[w] + (s - v);
        if (i < N_NODES) offs[i] = excl;
        __syncthreads();
        if (threadIdx.x == 0) s_running += s_chunk;
        __syncthreads();
    }
    if (threadIdx.x == 0) offs[N_NODES] = s_running;
}

// ---------------- cursor init ----------------------------------------------------
__global__ void cursor_kernel() {
    int i = blockIdx.x * blockDim.x + threadIdx.x;
    if (i < 2 * N_NODES) {
        int g = i / N_NODES, n = i - g * N_NODES;
        g_cursor[i] = g_offs[g * (N_NODES + 1) + n];
    }
}

// ---------------- scatter edges into CSR ----------------------------------------
__global__ void scatter_kernel(const int* __restrict__ e1, const int* __restrict__ e2) {
    int g = blockIdx.y;
    const int* ei = g ? e2 : e1;
    int i = blockIdx.x * blockDim.x + threadIdx.x;
    if (i < N_EDGES) {
        int s = ei[i];
        int d = ei[N_EDGES + i];
        int p = atomicAdd(&g_cursor[g * N_NODES + d], 1);
        g_csr[g * N_EDGES + p] = s;
    }
}

// ---------------- gather aggregation: agg[n] = mean of x[src] -------------------
__global__ void agg_kernel(const float* __restrict__ x0, const float* __restrict__ x1,
                           int in_sel) {
    int g = blockIdx.y;
    int warp = (blockIdx.x * blockDim.x + threadIdx.x) >> 5;
    int lane = threadIdx.x & 31;
    if (warp >= N_NODES) return;
    const float* xp = (in_sel < 0) ? (g ? x1 : x0) : g_xbuf[in_sel][g];
    const float4* x = (const float4*)xp;
    const int* offs = g_offs + g * (N_NODES + 1);
    const int* csr = g_csr + g * N_EDGES;
    int s = offs[warp], e = offs[warp + 1];
    float4 acc = make_float4(0.f, 0.f, 0.f, 0.f);
    for (int j = s; j < e; j++) {
        int src = csr[j];
        float4 t = x[src * 32 + lane];
        acc.x += t.x; acc.y += t.y; acc.z += t.z; acc.w += t.w;
    }
    int d = e - s; if (d < 1) d = 1;
    float inv = 1.0f / (float)d;
    acc.x *= inv; acc.y *= inv; acc.z *= inv; acc.w *= inv;
    ((float4*)g_agg[g])[warp * 32 + lane] = acc;
}

// ---------------- fused [N,256]@[256,128] + bias + BN + ReLU --------------------
#define GEMM_SMEM ((256 * 128 + 64 * 257) * 4)
__global__ void __launch_bounds__(256)
gemm_kernel(const float* __restrict__ x0, const float* __restrict__ x1,
            const float* __restrict__ Wl, const float* __restrict__ Wr,
            const float* __restrict__ bl,
            const float* __restrict__ gam, const float* __restrict__ bet,
            const float* __restrict__ mean, const float* __restrict__ var,
            int in_sel, int out_sel) {
    int g = blockIdx.y;
    const float* x = (in_sel < 0) ? (g ? x1 : x0) : g_xbuf[in_sel][g];
    float* out = g_xbuf[out_sel][g];
    const float* agg = g_agg[g];

    extern __shared__ float sm[];
    float* Wsm = sm;               // [256][128]
    float* Ism = sm + 256 * 128;   // [64][257]
    int tid = threadIdx.x;

    // load weights: rows 0..127 = Wl, 128..255 = Wr
    for (int idx = tid; idx < 8192; idx += 256) {
        int k = idx >> 5;
        int cg = idx & 31;
        const float* srcp = (k < 128) ? (Wl + k * 128 + cg * 4)
                                      : (Wr + (k - 128) * 128 + cg * 4);
        float4 w = *(const float4*)srcp;
        *(float4*)&Wsm[k * 128 + cg * 4] = w;
    }
    // load input tile: cols 0..127 = agg row, 128..255 = x row
    int row0 = blockIdx.x * 64;
    for (int idx = tid; idx < 4096; idx += 256) {
        int r = idx >> 6;
        int part = idx & 63;
        int row = row0 + r;
        float4 vv = make_float4(0.f, 0.f, 0.f, 0.f);
        if (row < N_NODES) {
            if (part < 32) vv = ((const float4*)agg)[row * 32 + part];
            else           vv = ((const float4*)x)[row * 32 + (part - 32)];
        }
        int k0 = part * 4;
        float* dst = &Ism[r * 257 + k0];
        dst[0] = vv.x; dst[1] = vv.y; dst[2] = vv.z; dst[3] = vv.w;
    }
    __syncthreads();

    int tx = tid & 31, ty = tid >> 5;
    float acc[8][4];
    #pragma unroll
    for (int i = 0; i < 8; i++)
        #pragma unroll
        for (int j = 0; j < 4; j++) acc[i][j] = 0.f;

    #pragma unroll 4
    for (int k = 0; k < 256; k++) {
        float4 w = *(const float4*)&Wsm[k * 128 + tx * 4];
        #pragma unroll
        for (int i = 0; i < 8; i++) {
            float a = Ism[(ty + 8 * i) * 257 + k];
            acc[i][0] += a * w.x;
            acc[i][1] += a * w.y;
            acc[i][2] += a * w.z;
            acc[i][3] += a * w.w;
        }
    }

    // epilogue: bias + batchnorm (eval) + relu
    int c0 = tx * 4;
    float sc[4], sh[4];
    #pragma unroll
    for (int j = 0; j < 4; j++) {
        int c = c0 + j;
        float s = gam[c] * rsqrtf(var[c] + EPSBN);
        sc[j] = s;
        sh[j] = (bl[c] - mean[c]) * s + bet[c];
    }
    #pragma unroll
    for (int i = 0; i < 8; i++) {
        int row = row0 + ty + 8 * i;
        if (row < N_NODES) {
            float4 o;
            o.x = fmaxf(acc[i][0] * sc[0] + sh[0], 0.f);
            o.y = fmaxf(acc[i][1] * sc[1] + sh[1], 0.f);
            o.z = fmaxf(acc[i][2] * sc[2] + sh[2], 0.f);
            o.w = fmaxf(acc[i][3] * sc[3] + sh[3], 0.f);
            *(float4*)&out[row * 128 + c0] = o;
        }
    }
}

// ---------------- global add pool ------------------------------------------------
__global__ void pool_kernel(const int* __restrict__ batch0, const int* __restrict__ batch1,
                            int in_sel) {
    int g = blockIdx.y;
    int warp = (blockIdx.x * blockDim.x + threadIdx.x) >> 5;
    int lane = threadIdx.x & 31;
    if (warp >= N_NODES) return;
    const float* xf = g_xbuf[in_sel][g];
    int b = (g ? batch1 : batch0)[warp];
    float4 v = ((const float4*)xf)[warp * 32 + lane];
    float* p = &g_pool[g][b * 128 + lane * 4];
    atomicAdd(p + 0, v.x);
    atomicAdd(p + 1, v.y);
    atomicAdd(p + 2, v.z);
    atomicAdd(p + 3, v.w);
}

// ---------------- final MLP: [B,384]@[384,128] -> relu -> @[128,1] ---------------
__global__ void __launch_bounds__(128)
mlp_kernel(const int* __restrict__ rel, const float* __restrict__ kge,
           const float* __restrict__ W1, const float* __restrict__ b1,
           const float* __restrict__ W2, const float* __restrict__ b2,
           float* __restrict__ out) {
    __shared__ float zsm[8][384];
    __shared__ float red[8][4];
    int tid = threadIdx.x;
    int b0 = blockIdx.x * 8;
    #pragma unroll
    for (int j = 0; j < 8; j++) {
        int b = b0 + j;
        zsm[j][tid]       = g_pool[0][b * 128 + tid];
        zsm[j][128 + tid] = g_pool[1][b * 128 + tid];
        zsm[j][256 + tid] = kge[rel[b] * 128 + tid];
    }
    __syncthreads();
    float acc[8];
    float bias = b1[tid];
    #pragma unroll
    for (int j = 0; j < 8; j++) acc[j] = bias;
    for (int k = 0; k < 384; k++) {
        float w = W1[k * 128 + tid];
        #pragma unroll
        for (int j = 0; j < 8; j++) acc[j] += zsm[j][k] * w;
    }
    float w2 = W2[tid];
    #pragma unroll
    for (int j = 0; j < 8; j++) {
        float h = fmaxf(acc[j], 0.f) * w2;
        #pragma unroll
        for (int o = 16; o > 0; o >>= 1) h += __shfl_down_sync(0xffffffffu, h, o);
        if ((tid & 31) == 0) red[j][tid >> 5] = h;
    }
    __syncthreads();
    if (tid < 8)
        out[b0 + tid] = red[tid][0] + red[tid][1] + red[tid][2] + red[tid][3] + b2[0];
}

// ---------------- host launcher ---------------------------------------------------
extern "C" void kernel_launch(void* const* d_in, const int* in_sizes, int n_in,
                              void* d_out, int out_size) {
    // Detect input ordering. x arrays have 6,400,000 elements; edge_index 1,200,000.
    int ix1 = 0, ie1, ib1, ix2, ie2, ib2;
    if (in_sizes[1] == 2 * N_EDGES) {           // reference-signature order
        ie1 = 1; ib1 = 2; ix2 = 3; ie2 = 4; ib2 = 5;
    } else {                                    // setup_inputs dict order
        ix2 = 1; ie1 = 2; ie2 = 3; ib1 = 4; ib2 = 5;
    }
    const float* x1     = (const float*)d_in[ix1];
    const float* x2     = (const float*)d_in[ix2];
    const int*   e1     = (const int*)d_in[ie1];
    const int*   e2     = (const int*)d_in[ie2];
    const int*   batch1 = (const int*)d_in[ib1];
    const int*   batch2 = (const int*)d_in[ib2];
    const int*   rel    = (const int*)d_in[6];
    const float* Wl     = (const float*)d_in[7];
    const float* bl     = (const float*)d_in[8];
    const float* Wr     = (const float*)d_in[9];
    const float* gam    = (const float*)d_in[10];
    const float* bet    = (const float*)d_in[11];
    const float* mean   = (const float*)d_in[12];
    const float* var    = (const float*)d_in[13];
    const float* kge    = (const float*)d_in[14];
    const float* W1     = (const float*)d_in[15];
    const float* b1     = (const float*)d_in[16];
    const float* W2     = (const float*)d_in[17];
    const float* b2     = (const float*)d_in[18];
    float* out = (float*)d_out;

    cudaFuncSetAttribute(gemm_kernel, cudaFuncAttributeMaxDynamicSharedMemorySize, GEMM_SMEM);

    zero_kernel<<<256, 256>>>();

    dim3 gE((N_EDGES + 255) / 256, 2);
    hist_kernel<<<gE, 256>>>(e1, e2);
    scan_kernel<<<2, 1024>>>();
    cursor_kernel<<<(2 * N_NODES + 255) / 256, 256>>>();
    scatter_kernel<<<gE, 256>>>(e1, e2);

    dim3 gWarp((N_NODES + 7) / 8, 2);      // 8 warps (one node each) per block
    dim3 gGemm((N_NODES + 63) / 64, 2);

    int in_sel = -1;
    int out_sel = 0;
    for (int l = 0; l < L_IT; l++) {
        const float* Wl_l = Wl + l * DIM * DIM;
        const float* Wr_l = Wr + l * DIM * DIM;
        agg_kernel<<<gWarp, 256>>>(x1, x2, in_sel);
        gemm_kernel<<<gGemm, 256, GEMM_SMEM>>>(x1, x2, Wl_l, Wr_l,
                                               bl + l * DIM,
                                               gam + l * DIM, bet + l * DIM,
                                               mean + l * DIM, var + l * DIM,
                                               in_sel, out_sel);
        in_sel = out_sel;
        out_sel ^= 1;
    }

    pool_kernel<<<gWarp, 256>>>(batch1, batch2, in_sel);
    mlp_kernel<<<B_GR / 8, 128>>>(rel, kge, W1, b1, W2, b2, out);
    (void)n_in; (void)out_size;
}

// round 5
// speedup vs baseline: 1.2623x; 1.2623x over previous
#include <cuda_runtime.h>

#define N_NODES 50000
#define N_EDGES 600000
#define B_GR    4096
#define DIM     128
#define L_IT    3
#define EPSBN   1e-5f

// ---------------- device scratch (static globals: allocation-free) -------------
__device__ int   g_deg[2 * N_NODES];
__device__ int   g_offs[2 * (N_NODES + 1)];
__device__ int   g_cursor[2 * N_NODES];
__device__ int   g_csr[2 * N_EDGES];
__device__ float g_agg[2][N_NODES * DIM];
__device__ float g_xbuf[2][2][N_NODES * DIM];   // [pingpong][graph]
__device__ float g_pool[2][B_GR * DIM];

// ---------------- tf32 helpers ---------------------------------------------------
__device__ __forceinline__ unsigned f2tf32(float x) {
    unsigned r;
    asm("cvt.rna.tf32.f32 %0, %1;" : "=r"(r) : "f"(x));
    return r;
}

__device__ __forceinline__ void mma_tf32(float c[4],
                                         unsigned a0, unsigned a1, unsigned a2, unsigned a3,
                                         unsigned b0, unsigned b1) {
    asm volatile(
        "mma.sync.aligned.m16n8k8.row.col.f32.tf32.tf32.f32 "
        "{%0,%1,%2,%3},{%4,%5,%6,%7},{%8,%9},{%0,%1,%2,%3};"
        : "+f"(c[0]), "+f"(c[1]), "+f"(c[2]), "+f"(c[3])
        : "r"(a0), "r"(a1), "r"(a2), "r"(a3), "r"(b0), "r"(b1));
}

// ---------------- zero deg + pool ------------------------------------------------
__global__ void zero_kernel() {
    int i = blockIdx.x * blockDim.x + threadIdx.x;
    int stride = gridDim.x * blockDim.x;
    for (int j = i; j < 2 * N_NODES; j += stride) g_deg[j] = 0;
    float* p = &g_pool[0][0];
    for (int j = i; j < 2 * B_GR * DIM; j += stride) p[j] = 0.0f;
}

// ---------------- histogram of in-degrees ---------------------------------------
__global__ void hist_kernel(const int* __restrict__ e1, const int* __restrict__ e2) {
    int g = blockIdx.y;
    const int* dst = (g ? e2 : e1) + N_EDGES;
    int i = blockIdx.x * blockDim.x + threadIdx.x;
    if (i < N_EDGES) atomicAdd(&g_deg[g * N_NODES + dst[i]], 1);
}

// ---------------- single-block exclusive scan per graph -------------------------
__global__ void scan_kernel() {
    int g = blockIdx.x;
    const int* deg = g_deg + g * N_NODES;
    int* offs = g_offs + g * (N_NODES + 1);
    __shared__ int warpsum[32];
    __shared__ int s_running;
    __shared__ int s_chunk;
    if (threadIdx.x == 0) s_running = 0;
    __syncthreads();
    int lane = threadIdx.x & 31, w = threadIdx.x >> 5;
    for (int base = 0; base < N_NODES; base += 1024) {
        int i = base + threadIdx.x;
        int v = (i < N_NODES) ? deg[i] : 0;
        int s = v;
        #pragma unroll
        for (int o = 1; o < 32; o <<= 1) {
            int t = __shfl_up_sync(0xffffffffu, s, o);
            if (lane >= o) s += t;
        }
        if (lane == 31) warpsum[w] = s;
        __syncthreads();
        if (w == 0) {
            int ws = warpsum[lane];
            int ss = ws;
            #pragma unroll
            for (int o = 1; o < 32; o <<= 1) {
                int t = __shfl_up_sync(0xffffffffu, ss, o);
                if (lane >= o) ss += t;
            }
            if (lane == 31) s_chunk = ss;
            warpsum[lane] = ss - ws;   // exclusive warp offset
        }
        __syncthreads();
        int excl = s_running + warpsum[w] + (s - v);
        if (i < N_NODES) offs[i] = excl;
        __syncthreads();
        if (threadIdx.x == 0) s_running += s_chunk;
        __syncthreads();
    }
    if (threadIdx.x == 0) offs[N_NODES] = s_running;
}

// ---------------- cursor init ----------------------------------------------------
__global__ void cursor_kernel() {
    int i = blockIdx.x * blockDim.x + threadIdx.x;
    if (i < 2 * N_NODES) {
        int g = i / N_NODES, n = i - g * N_NODES;
        g_cursor[i] = g_offs[g * (N_NODES + 1) + n];
    }
}

// ---------------- scatter edges into CSR ----------------------------------------
__global__ void scatter_kernel(const int* __restrict__ e1, const int* __restrict__ e2) {
    int g = blockIdx.y;
    const int* ei = g ? e2 : e1;
    int i = blockIdx.x * blockDim.x + threadIdx.x;
    if (i < N_EDGES) {
        int s = ei[i];
        int d = ei[N_EDGES + i];
        int p = atomicAdd(&g_cursor[g * N_NODES + d], 1);
        g_csr[g * N_EDGES + p] = s;
    }
}

// ---------------- gather aggregation: agg[n] = mean of x[src] -------------------
__global__ void agg_kernel(const float* __restrict__ x0, const float* __restrict__ x1,
                           int in_sel) {
    int g = blockIdx.y;
    int warp = (blockIdx.x * blockDim.x + threadIdx.x) >> 5;
    int lane = threadIdx.x & 31;
    if (warp >= N_NODES) return;
    const float* xp = (in_sel < 0) ? (g ? x1 : x0) : g_xbuf[in_sel][g];
    const float4* x = (const float4*)xp;
    const int* offs = g_offs + g * (N_NODES + 1);
    const int* csr = g_csr + g * N_EDGES;
    int s = offs[warp], e = offs[warp + 1];
    float4 acc = make_float4(0.f, 0.f, 0.f, 0.f);
    for (int j = s; j < e; j++) {
        int src = csr[j];
        float4 t = x[src * 32 + lane];
        acc.x += t.x; acc.y += t.y; acc.z += t.z; acc.w += t.w;
    }
    int d = e - s; if (d < 1) d = 1;
    float inv = 1.0f / (float)d;
    acc.x *= inv; acc.y *= inv; acc.z *= inv; acc.w *= inv;
    ((float4*)g_agg[g])[warp * 32 + lane] = acc;
}

// ---------------- tf32x3 tensor-core GEMM ----------------------------------------
// C[128 x 128] tile = A[128 x 256] @ W[256 x 128], A = [agg | x] per row.
// W kept transposed in smem (n-major, stride 260 -> conflict-free B frag loads).
// A streamed in K=32 chunks, double buffered, stride 36 -> conflict-free A frags.
#define WT_ST 260
#define A_ST  36
#define GEMM_SMEM ((128 * WT_ST + 2 * 128 * A_ST + 256) * 4)

__global__ void __launch_bounds__(256)
gemm_kernel(const float* __restrict__ x0, const float* __restrict__ x1,
            const float* __restrict__ Wl, const float* __restrict__ Wr,
            const float* __restrict__ bl,
            const float* __restrict__ gam, const float* __restrict__ bet,
            const float* __restrict__ mean, const float* __restrict__ var,
            int in_sel, int out_sel) {
    int g = blockIdx.y;
    const float* x = (in_sel < 0) ? (g ? x1 : x0) : g_xbuf[in_sel][g];
    float* out = g_xbuf[out_sel][g];
    const float* agg = g_agg[g];

    extern __shared__ float sm[];
    float* Wt  = sm;                       // [128 n][260] (k index inside)
    float* Asm = sm + 128 * WT_ST;         // 2 buffers of [128 rows][36]
    float* ssc = Asm + 2 * 128 * A_ST;     // [128]
    float* ssh = ssc + 128;                // [128]

    int tid = threadIdx.x;
    int lane = tid & 31, wid = tid >> 5;
    int gp = lane >> 2, tig = lane & 3;
    int warp_m = (wid & 3) * 32;           // 4 warps along M
    int warp_n = (wid >> 2) * 64;          // 2 warps along N
    int row0 = blockIdx.x * 128;

    // BN scale/shift per output column
    if (tid < 128) {
        float s = gam[tid] * rsqrtf(var[tid] + EPSBN);
        ssc[tid] = s;
        ssh[tid] = (bl[tid] - mean[tid]) * s + bet[tid];
    }

    // Load W transposed: Wt[n][k], k<128 from Wl, k>=128 from Wr
    for (int idx = tid; idx < 8192; idx += 256) {
        int k = idx >> 5;
        int n4 = idx & 31;
        const float* srcp = (k < 128) ? (Wl + k * 128 + n4 * 4)
                                      : (Wr + (k - 128) * 128 + n4 * 4);
        float4 w = *(const float4*)srcp;
        int n0 = n4 * 4;
        Wt[(n0 + 0) * WT_ST + k] = w.x;
        Wt[(n0 + 1) * WT_ST + k] = w.y;
        Wt[(n0 + 2) * WT_ST + k] = w.z;
        Wt[(n0 + 3) * WT_ST + k] = w.w;
    }

    auto load_chunk = [&](int buf, int kc) {
        float* dst = Asm + buf * 128 * A_ST;
        const float* srcbase = (kc < 4) ? agg : x;
        int coff = (kc & 3) * 32;
        #pragma unroll
        for (int i = tid; i < 1024; i += 256) {
            int r = i >> 3, c4 = i & 7;
            float4 v = make_float4(0.f, 0.f, 0.f, 0.f);
            if (row0 + r < N_NODES)
                v = *(const float4*)(srcbase + (row0 + r) * 128 + coff + c4 * 4);
            float* d = dst + r * A_ST + c4 * 4;
            d[0] = v.x; d[1] = v.y; d[2] = v.z; d[3] = v.w;
        }
    };

    load_chunk(0, 0);
    __syncthreads();

    float acc[2][8][4];
    #pragma unroll
    for (int mt = 0; mt < 2; mt++)
        #pragma unroll
        for (int n8 = 0; n8 < 8; n8++)
            #pragma unroll
            for (int j = 0; j < 4; j++) acc[mt][n8][j] = 0.f;

    int cur = 0;
    for (int kc = 0; kc < 8; kc++) {
        if (kc + 1 < 8) load_chunk(cur ^ 1, kc + 1);
        const float* Ab = Asm + cur * 128 * A_ST;
        #pragma unroll
        for (int k8 = 0; k8 < 4; k8++) {
            int kk = k8 * 8;
            unsigned ah[2][4], al[2][4];
            #pragma unroll
            for (int mt = 0; mt < 2; mt++) {
                int r = warp_m + mt * 16 + gp;
                float a0 = Ab[r * A_ST + kk + tig];
                float a1 = Ab[(r + 8) * A_ST + kk + tig];
                float a2 = Ab[r * A_ST + kk + tig + 4];
                float a3 = Ab[(r + 8) * A_ST + kk + tig + 4];
                ah[mt][0] = f2tf32(a0); al[mt][0] = f2tf32(a0 - __uint_as_float(ah[mt][0]));
                ah[mt][1] = f2tf32(a1); al[mt][1] = f2tf32(a1 - __uint_as_float(ah[mt][1]));
                ah[mt][2] = f2tf32(a2); al[mt][2] = f2tf32(a2 - __uint_as_float(ah[mt][2]));
                ah[mt][3] = f2tf32(a3); al[mt][3] = f2tf32(a3 - __uint_as_float(ah[mt][3]));
            }
            int kg = kc * 32 + kk;
            #pragma unroll
            for (int n8 = 0; n8 < 8; n8++) {
                int n = warp_n + n8 * 8 + gp;
                float b0f = Wt[n * WT_ST + kg + tig];
                float b1f = Wt[n * WT_ST + kg + tig + 4];
                unsigned bh0 = f2tf32(b0f);
                unsigned bl0 = f2tf32(b0f - __uint_as_float(bh0));
                unsigned bh1 = f2tf32(b1f);
                unsigned bl1 = f2tf32(b1f - __uint_as_float(bh1));
                #pragma unroll
                for (int mt = 0; mt < 2; mt++) {
                    mma_tf32(acc[mt][n8], ah[mt][0], ah[mt][1], ah[mt][2], ah[mt][3], bh0, bh1);
                    mma_tf32(acc[mt][n8], al[mt][0], al[mt][1], al[mt][2], al[mt][3], bh0, bh1);
                    mma_tf32(acc[mt][n8], ah[mt][0], ah[mt][1], ah[mt][2], ah[mt][3], bl0, bl1);
                }
            }
        }
        __syncthreads();
        cur ^= 1;
    }

    // epilogue: BN (eval, bias folded) + relu
    #pragma unroll
    for (int mt = 0; mt < 2; mt++) {
        int ra = row0 + warp_m + mt * 16 + gp;
        int rb = ra + 8;
        #pragma unroll
        for (int n8 = 0; n8 < 8; n8++) {
            int col = warp_n + n8 * 8 + 2 * tig;
            float s0 = ssc[col], s1 = ssc[col + 1];
            float h0 = ssh[col], h1 = ssh[col + 1];
            if (ra < N_NODES) {
                float2 o;
                o.x = fmaxf(acc[mt][n8][0] * s0 + h0, 0.f);
                o.y = fmaxf(acc[mt][n8][1] * s1 + h1, 0.f);
                *(float2*)&out[ra * 128 + col] = o;
            }
            if (rb < N_NODES) {
                float2 o;
                o.x = fmaxf(acc[mt][n8][2] * s0 + h0, 0.f);
                o.y = fmaxf(acc[mt][n8][3] * s1 + h1, 0.f);
                *(float2*)&out[rb * 128 + col] = o;
            }
        }
    }
}

// ---------------- global add pool ------------------------------------------------
__global__ void pool_kernel(const int* __restrict__ batch0, const int* __restrict__ batch1,
                            int in_sel) {
    int g = blockIdx.y;
    int warp = (blockIdx.x * blockDim.x + threadIdx.x) >> 5;
    int lane = threadIdx.x & 31;
    if (warp >= N_NODES) return;
    const float* xf = g_xbuf[in_sel][g];
    int b = (g ? batch1 : batch0)[warp];
    float4 v = ((const float4*)xf)[warp * 32 + lane];
    float* p = &g_pool[g][b * 128 + lane * 4];
    atomicAdd(p + 0, v.x);
    atomicAdd(p + 1, v.y);
    atomicAdd(p + 2, v.z);
    atomicAdd(p + 3, v.w);
}

// ---------------- final MLP: [B,384]@[384,128] -> relu -> @[128,1] ---------------
__global__ void __launch_bounds__(128)
mlp_kernel(const int* __restrict__ rel, const float* __restrict__ kge,
           const float* __restrict__ W1, const float* __restrict__ b1,
           const float* __restrict__ W2, const float* __restrict__ b2,
           float* __restrict__ out) {
    __shared__ float zsm[8][384];
    __shared__ float red[8][4];
    int tid = threadIdx.x;
    int b0 = blockIdx.x * 8;
    #pragma unroll
    for (int j = 0; j < 8; j++) {
        int b = b0 + j;
        zsm[j][tid]       = g_pool[0][b * 128 + tid];
        zsm[j][128 + tid] = g_pool[1][b * 128 + tid];
        zsm[j][256 + tid] = kge[rel[b] * 128 + tid];
    }
    __syncthreads();
    float acc[8];
    float bias = b1[tid];
    #pragma unroll
    for (int j = 0; j < 8; j++) acc[j] = bias;
    for (int k = 0; k < 384; k++) {
        float w = W1[k * 128 + tid];
        #pragma unroll
        for (int j = 0; j < 8; j++) acc[j] += zsm[j][k] * w;
    }
    float w2 = W2[tid];
    #pragma unroll
    for (int j = 0; j < 8; j++) {
        float h = fmaxf(acc[j], 0.f) * w2;
        #pragma unroll
        for (int o = 16; o > 0; o >>= 1) h += __shfl_down_sync(0xffffffffu, h, o);
        if ((tid & 31) == 0) red[j][tid >> 5] = h;
    }
    __syncthreads();
    if (tid < 8)
        out[b0 + tid] = red[tid][0] + red[tid][1] + red[tid][2] + red[tid][3] + b2[0];
}

// ---------------- host launcher ---------------------------------------------------
extern "C" void kernel_launch(void* const* d_in, const int* in_sizes, int n_in,
                              void* d_out, int out_size) {
    // Detect input ordering. x arrays have 6,400,000 elements; edge_index 1,200,000.
    int ix1 = 0, ie1, ib1, ix2, ie2, ib2;
    if (in_sizes[1] == 2 * N_EDGES) {           // reference-signature order
        ie1 = 1; ib1 = 2; ix2 = 3; ie2 = 4; ib2 = 5;
    } else {                                    // setup_inputs dict order
        ix2 = 1; ie1 = 2; ie2 = 3; ib1 = 4; ib2 = 5;
    }
    const float* x1     = (const float*)d_in[ix1];
    const float* x2     = (const float*)d_in[ix2];
    const int*   e1     = (const int*)d_in[ie1];
    const int*   e2     = (const int*)d_in[ie2];
    const int*   batch1 = (const int*)d_in[ib1];
    const int*   batch2 = (const int*)d_in[ib2];
    const int*   rel    = (const int*)d_in[6];
    const float* Wl     = (const float*)d_in[7];
    const float* bl     = (const float*)d_in[8];
    const float* Wr     = (const float*)d_in[9];
    const float* gam    = (const float*)d_in[10];
    const float* bet    = (const float*)d_in[11];
    const float* mean   = (const float*)d_in[12];
    const float* var    = (const float*)d_in[13];
    const float* kge    = (const float*)d_in[14];
    const float* W1     = (const float*)d_in[15];
    const float* b1     = (const float*)d_in[16];
    const float* W2     = (const float*)d_in[17];
    const float* b2     = (const float*)d_in[18];
    float* out = (float*)d_out;

    static int attr_done = 0;
    if (!attr_done) {
        cudaFuncSetAttribute(gemm_kernel, cudaFuncAttributeMaxDynamicSharedMemorySize,
                             GEMM_SMEM);
        attr_done = 1;
    }

    zero_kernel<<<256, 256>>>();

    dim3 gE((N_EDGES + 255) / 256, 2);
    hist_kernel<<<gE, 256>>>(e1, e2);
    scan_kernel<<<2, 1024>>>();
    cursor_kernel<<<(2 * N_NODES + 255) / 256, 256>>>();
    scatter_kernel<<<gE, 256>>>(e1, e2);

    dim3 gWarp((N_NODES + 7) / 8, 2);      // 8 warps (one node each) per block
    dim3 gGemm((N_NODES + 127) / 128, 2);

    int in_sel = -1;
    int out_sel = 0;
    for (int l = 0; l < L_IT; l++) {
        const float* Wl_l = Wl + l * DIM * DIM;
        const float* Wr_l = Wr + l * DIM * DIM;
        agg_kernel<<<gWarp, 256>>>(x1, x2, in_sel);
        gemm_kernel<<<gGemm, 256, GEMM_SMEM>>>(x1, x2, Wl_l, Wr_l,
                                               bl + l * DIM,
                                               gam + l * DIM, bet + l * DIM,
                                               mean + l * DIM, var + l * DIM,
                                               in_sel, out_sel);
        in_sel = out_sel;
        out_sel ^= 1;
    }

    pool_kernel<<<gWarp, 256>>>(batch1, batch2, in_sel);
    mlp_kernel<<<B_GR / 8, 128>>>(rel, kge, W1, b1, W2, b2, out);
    (void)n_in; (void)out_size;
}

// round 12
// speedup vs baseline: 2.1238x; 1.6826x over previous
#include <cuda_runtime.h>
#include <cuda_bf16.h>
#include <cstdint>

#define N_NODES 50000
#define N_EDGES 600000
#define B_GR    4096
#define DIM     128
#define L_IT    3
#define EPSBN   1e-5f

// ---------------- device scratch (static globals: allocation-free) -------------
__device__ int   g_deg[2 * N_NODES];
__device__ int   g_offs[2 * (N_NODES + 1)];
__device__ int   g_cursor[2 * N_NODES];
__device__ int   g_csr[2 * N_EDGES];
__device__ float g_agg[2][N_NODES * DIM];
__device__ float g_xbuf[2][2][N_NODES * DIM];   // [pingpong][graph]
__device__ float g_pool[2][B_GR * DIM];
// W split into bf16 b0/b1 planes, n-major [n][k] (k: 0-127 Wl, 128-255 Wr)
__device__ __nv_bfloat16 g_wb[L_IT][2][128][256];

// pack two floats into a bf16x2 word (round-to-nearest)
__device__ __forceinline__ uint32_t pack_bf2(float lo, float hi) {
    uint16_t l = __bfloat16_as_ushort(__float2bfloat16(lo));
    uint16_t h = __bfloat16_as_ushort(__float2bfloat16(hi));
    return (uint32_t)l | ((uint32_t)h << 16);
}
__device__ __forceinline__ float bf_hi_part(float v) {
    // value of bf16(v) as float
    return __bfloat162float(__float2bfloat16(v));
}

// ---------------- zero deg + pool ------------------------------------------------
__global__ void zero_kernel() {
    int i = blockIdx.x * blockDim.x + threadIdx.x;
    int stride = gridDim.x * blockDim.x;
    for (int j = i; j < 2 * N_NODES; j += stride) g_deg[j] = 0;
    float* p = &g_pool[0][0];
    for (int j = i; j < 2 * B_GR * DIM; j += stride) p[j] = 0.0f;
}

// ---------------- W split into bf16 b0/b1 planes ---------------------------------
__global__ void wsplit_kernel(const float* __restrict__ Wl, const float* __restrict__ Wr) {
    int idx = blockIdx.x * blockDim.x + threadIdx.x;   // [l][n][k]
    if (idx >= L_IT * 128 * 256) return;
    int k = idx & 255;
    int n = (idx >> 8) & 127;
    int l = idx >> 15;
    float v = (k < 128) ? Wl[(l * 128 + k) * 128 + n]
                        : Wr[(l * 128 + (k - 128)) * 128 + n];
    __nv_bfloat16 b0 = __float2bfloat16(v);
    __nv_bfloat16 b1 = __float2bfloat16(v - __bfloat162float(b0));
    g_wb[l][0][n][k] = b0;
    g_wb[l][1][n][k] = b1;
}

// ---------------- histogram of in-degrees ---------------------------------------
__global__ void hist_kernel(const int* __restrict__ e1, const int* __restrict__ e2) {
    int g = blockIdx.y;
    const int* dst = (g ? e2 : e1) + N_EDGES;
    int i = blockIdx.x * blockDim.x + threadIdx.x;
    if (i < N_EDGES) atomicAdd(&g_deg[g * N_NODES + dst[i]], 1);
}

// ---------------- single-block exclusive scan per graph (writes offs + cursor) ---
__global__ void scan_kernel() {
    int g = blockIdx.x;
    const int* deg = g_deg + g * N_NODES;
    int* offs = g_offs + g * (N_NODES + 1);
    int* cur  = g_cursor + g * N_NODES;
    __shared__ int warpsum[32];
    __shared__ int s_running;
    __shared__ int s_chunk;
    if (threadIdx.x == 0) s_running = 0;
    __syncthreads();
    int lane = threadIdx.x & 31, w = threadIdx.x >> 5;
    for (int base = 0; base < N_NODES; base += 1024) {
        int i = base + threadIdx.x;
        int v = (i < N_NODES) ? deg[i] : 0;
        int s = v;
        #pragma unroll
        for (int o = 1; o < 32; o <<= 1) {
            int t = __shfl_up_sync(0xffffffffu, s, o);
            if (lane >= o) s += t;
        }
        if (lane == 31) warpsum[w] = s;
        __syncthreads();
        if (w == 0) {
            int ws = warpsum[lane];
            int ss = ws;
            #pragma unroll
            for (int o = 1; o < 32; o <<= 1) {
                int t = __shfl_up_sync(0xffffffffu, ss, o);
                if (lane >= o) ss += t;
            }
            if (lane == 31) s_chunk = ss;
            warpsum[lane] = ss - ws;
        }
        __syncthreads();
        int excl = s_running + warpsum[w] + (s - v);
        if (i < N_NODES) { offs[i] = excl; cur[i] = excl; }
        __syncthreads();
        if (threadIdx.x == 0) s_running += s_chunk;
        __syncthreads();
    }
    if (threadIdx.x == 0) offs[N_NODES] = s_running;
}

// ---------------- scatter edges into CSR ----------------------------------------
__global__ void scatter_kernel(const int* __restrict__ e1, const int* __restrict__ e2) {
    int g = blockIdx.y;
    const int* ei = g ? e2 : e1;
    int i = blockIdx.x * blockDim.x + threadIdx.x;
    if (i < N_EDGES) {
        int s = ei[i];
        int d = ei[N_EDGES + i];
        int p = atomicAdd(&g_cursor[g * N_NODES + d], 1);
        g_csr[g * N_EDGES + p] = s;
    }
}

// ---------------- gather aggregation: agg[n] = mean of x[src] -------------------
__global__ void agg_kernel(const float* __restrict__ x0, const float* __restrict__ x1,
                           int in_sel) {
    int g = blockIdx.y;
    int warp = (blockIdx.x * blockDim.x + threadIdx.x) >> 5;
    int lane = threadIdx.x & 31;
    if (warp >= N_NODES) return;
    const float* xp = (in_sel < 0) ? (g ? x1 : x0) : g_xbuf[in_sel][g];
    const float4* x = (const float4*)xp;
    const int* offs = g_offs + g * (N_NODES + 1);
    const int* csr = g_csr + g * N_EDGES;
    int s = offs[warp], e = offs[warp + 1];
    float4 acc = make_float4(0.f, 0.f, 0.f, 0.f);
    for (int j = s; j < e; j++) {
        int src = csr[j];
        float4 t = x[src * 32 + lane];
        acc.x += t.x; acc.y += t.y; acc.z += t.z; acc.w += t.w;
    }
    int d = e - s; if (d < 1) d = 1;
    float inv = 1.0f / (float)d;
    acc.x *= inv; acc.y *= inv; acc.z *= inv; acc.w *= inv;
    ((float4*)g_agg[g])[warp * 32 + lane] = acc;
}

// ---------------- bf16x3 mma.sync GEMM -------------------------------------------
// C[128 x 128] = A[128 x 256] @ W[256 x 128], A = [agg | x].
// A split into bf16 hi/lo planes at chunk-store time (stride 40 bf16 -> 32 banks).
// W pre-split (wsplit) and loaded to smem once per block (stride 264 -> 32 banks).
// 3 mma terms per k16: Ahi*Bhi + Alo*Bhi + Ahi*Blo (~2^-16 accuracy).
#define SW_ST 264
#define SA_ST 40
#define W_PLANE (128 * SW_ST * 2)            // bytes per W plane
#define A_PLANE (128 * SA_ST * 2)            // bytes per A plane
#define A_BASE  (2 * W_PLANE)
#define A_BUF   (2 * A_PLANE)                // hi + lo
#define EX_BASE (A_BASE + 2 * A_BUF)
#define GSMEM   (EX_BASE + 1024)

__device__ __forceinline__ void mma_bf16(float c[4], const uint32_t a[4],
                                         uint32_t b0, uint32_t b1) {
    asm volatile(
        "mma.sync.aligned.m16n8k16.row.col.f32.bf16.bf16.f32 "
        "{%0,%1,%2,%3},{%4,%5,%6,%7},{%8,%9},{%0,%1,%2,%3};"
        : "+f"(c[0]), "+f"(c[1]), "+f"(c[2]), "+f"(c[3])
        : "r"(a[0]), "r"(a[1]), "r"(a[2]), "r"(a[3]), "r"(b0), "r"(b1));
}

__global__ void __launch_bounds__(256)
gemm_kernel(const float* __restrict__ x0, const float* __restrict__ x1,
            const float* __restrict__ bl,
            const float* __restrict__ gam, const float* __restrict__ bet,
            const float* __restrict__ mean, const float* __restrict__ var,
            int layer, int in_sel, int out_sel) {
    int g = blockIdx.y;
    const float* x = (in_sel < 0) ? (g ? x1 : x0) : g_xbuf[in_sel][g];
    const float* agg = g_agg[g];
    float* outp = g_xbuf[out_sel][g];

    extern __shared__ __align__(16) char sm[];
    char* sW0 = sm;                 // W b0 plane [128 n][264 k] bf16
    char* sW1 = sm + W_PLANE;       // W b1 plane
    float* ssc = (float*)(sm + EX_BASE);
    float* ssh = ssc + 128;

    int tid = threadIdx.x;
    int lane = tid & 31, wid = tid >> 5;
    int gp = lane >> 2, tig = lane & 3;
    int warp_m = (wid & 3) * 32;
    int warp_n = (wid >> 2) * 64;
    int row0 = blockIdx.x * 128;

    if (tid < 128) {
        float s = gam[tid] * rsqrtf(var[tid] + EPSBN);
        ssc[tid] = s;
        ssh[tid] = (bl[tid] - mean[tid]) * s + bet[tid];
    }

    // Load W planes (64KB each) into smem with stride 264 bf16 (= 528B rows)
    {
        const uint4* w0 = (const uint4*)&g_wb[layer][0][0][0];
        const uint4* w1 = (const uint4*)&g_wb[layer][1][0][0];
        #pragma unroll
        for (int t = 0; t < 16; t++) {
            int i = tid + t * 256;          // i in [0, 4096): [n][32 uint4]
            int n = i >> 5, c16 = i & 31;
            *(uint4*)(sW0 + n * (SW_ST * 2) + c16 * 16) = w0[i];
            *(uint4*)(sW1 + n * (SW_ST * 2) + c16 * 16) = w1[i];
        }
    }

    // A chunk staging: 128 rows x 32 k = 1024 float4, 4 per thread
    float4 stage[4];
    auto ldg_chunk = [&](int c) {
        const float* src = (c < 4) ? agg : x;
        int coff = (c & 3) * 32;
        #pragma unroll
        for (int t = 0; t < 4; t++) {
            int i = tid + t * 256;
            int r = i >> 3, c4 = i & 7;
            float4 v = make_float4(0.f, 0.f, 0.f, 0.f);
            int row = row0 + r;
            if (row < N_NODES) v = *(const float4*)(src + row * 128 + coff + c4 * 4);
            stage[t] = v;
        }
    };
    auto sts_chunk = [&](int buf) {
        char* hi = sm + A_BASE + buf * A_BUF;
        char* lo = hi + A_PLANE;
        #pragma unroll
        for (int t = 0; t < 4; t++) {
            int i = tid + t * 256;
            int r = i >> 3, c4 = i & 7;
            float4 v = stage[t];
            uint32_t h01 = pack_bf2(v.x, v.y);
            uint32_t h23 = pack_bf2(v.z, v.w);
            uint32_t l01 = pack_bf2(v.x - bf_hi_part(v.x), v.y - bf_hi_part(v.y));
            uint32_t l23 = pack_bf2(v.z - bf_hi_part(v.z), v.w - bf_hi_part(v.w));
            uint32_t off = r * (SA_ST * 2) + c4 * 8;
            *(uint2*)(hi + off) = make_uint2(h01, h23);
            *(uint2*)(lo + off) = make_uint2(l01, l23);
        }
    };

    ldg_chunk(0);
    sts_chunk(0);
    __syncthreads();

    float acc[2][8][4];
    #pragma unroll
    for (int mt = 0; mt < 2; mt++)
        #pragma unroll
        for (int n8 = 0; n8 < 8; n8++)
            #pragma unroll
            for (int j = 0; j < 4; j++) acc[mt][n8][j] = 0.f;

    for (int c = 0; c < 8; c++) {
        if (c + 1 < 8) ldg_chunk(c + 1);
        int buf = c & 1;
        const char* Ahi = sm + A_BASE + buf * A_BUF;
        const char* Alo = Ahi + A_PLANE;
        #pragma unroll
        for (int k16 = 0; k16 < 2; k16++) {
            int kloc = k16 * 16 + tig * 2;                 // bf16 units within chunk
            uint32_t ah[2][4], al[2][4];
            #pragma unroll
            for (int mt = 0; mt < 2; mt++) {
                int r = warp_m + mt * 16 + gp;
                uint32_t o00 = r * (SA_ST * 2) + kloc * 2;
                uint32_t o10 = o00 + 8 * (SA_ST * 2);
                ah[mt][0] = *(const uint32_t*)(Ahi + o00);
                ah[mt][1] = *(const uint32_t*)(Ahi + o10);
                ah[mt][2] = *(const uint32_t*)(Ahi + o00 + 16);
                ah[mt][3] = *(const uint32_t*)(Ahi + o10 + 16);
                al[mt][0] = *(const uint32_t*)(Alo + o00);
                al[mt][1] = *(const uint32_t*)(Alo + o10);
                al[mt][2] = *(const uint32_t*)(Alo + o00 + 16);
                al[mt][3] = *(const uint32_t*)(Alo + o10 + 16);
            }
            int kg = c * 32 + k16 * 16 + tig * 2;          // global k, bf16 units
            #pragma unroll
            for (int n8 = 0; n8 < 8; n8++) {
                int n = warp_n + n8 * 8 + gp;
                uint32_t wo = n * (SW_ST * 2) + kg * 2;
                uint32_t bh0 = *(const uint32_t*)(sW0 + wo);
                uint32_t bh1 = *(const uint32_t*)(sW0 + wo + 16);
                uint32_t bl0 = *(const uint32_t*)(sW1 + wo);
                uint32_t bl1 = *(const uint32_t*)(sW1 + wo + 16);
                #pragma unroll
                for (int mt = 0; mt < 2; mt++) {
                    mma_bf16(acc[mt][n8], ah[mt], bh0, bh1);
                    mma_bf16(acc[mt][n8], al[mt], bh0, bh1);
                    mma_bf16(acc[mt][n8], ah[mt], bl0, bl1);
                }
            }
        }
        __syncthreads();
        if (c + 1 < 8) {
            sts_chunk(buf ^ 1);
            __syncthreads();
        }
    }

    // epilogue: BN (eval, bias folded) + relu
    #pragma unroll
    for (int mt = 0; mt < 2; mt++) {
        int ra = row0 + warp_m + mt * 16 + gp;
        int rb = ra + 8;
        #pragma unroll
        for (int n8 = 0; n8 < 8; n8++) {
            int col = warp_n + n8 * 8 + 2 * tig;
            float s0 = ssc[col], s1 = ssc[col + 1];
            float h0 = ssh[col], h1 = ssh[col + 1];
            if (ra < N_NODES) {
                float2 o;
                o.x = fmaxf(acc[mt][n8][0] * s0 + h0, 0.f);
                o.y = fmaxf(acc[mt][n8][1] * s1 + h1, 0.f);
                *(float2*)&outp[ra * 128 + col] = o;
            }
            if (rb < N_NODES) {
                float2 o;
                o.x = fmaxf(acc[mt][n8][2] * s0 + h0, 0.f);
                o.y = fmaxf(acc[mt][n8][3] * s1 + h1, 0.f);
                *(float2*)&outp[rb * 128 + col] = o;
            }
        }
    }
}

// ---------------- global add pool ------------------------------------------------
__global__ void pool_kernel(const int* __restrict__ batch0, const int* __restrict__ batch1,
                            int in_sel) {
    int g = blockIdx.y;
    int warp = (blockIdx.x * blockDim.x + threadIdx.x) >> 5;
    int lane = threadIdx.x & 31;
    if (warp >= N_NODES) return;
    const float* xf = g_xbuf[in_sel][g];
    int b = (g ? batch1 : batch0)[warp];
    float4 v = ((const float4*)xf)[warp * 32 + lane];
    float* p = &g_pool[g][b * 128 + lane * 4];
    atomicAdd(p + 0, v.x);
    atomicAdd(p + 1, v.y);
    atomicAdd(p + 2, v.z);
    atomicAdd(p + 3, v.w);
}

// ---------------- final MLP: [B,384]@[384,128] -> relu -> @[128,1] ---------------
__global__ void __launch_bounds__(128)
mlp_kernel(const int* __restrict__ rel, const float* __restrict__ kge,
           const float* __restrict__ W1, const float* __restrict__ b1,
           const float* __restrict__ W2, const float* __restrict__ b2,
           float* __restrict__ out) {
    __shared__ float zsm[8][384];
    __shared__ float red[8][4];
    int tid = threadIdx.x;
    int b0 = blockIdx.x * 8;
    #pragma unroll
    for (int j = 0; j < 8; j++) {
        int b = b0 + j;
        zsm[j][tid]       = g_pool[0][b * 128 + tid];
        zsm[j][128 + tid] = g_pool[1][b * 128 + tid];
        zsm[j][256 + tid] = kge[rel[b] * 128 + tid];
    }
    __syncthreads();
    float acc[8];
    float bias = b1[tid];
    #pragma unroll
    for (int j = 0; j < 8; j++) acc[j] = bias;
    for (int k = 0; k < 384; k++) {
        float w = W1[k * 128 + tid];
        #pragma unroll
        for (int j = 0; j < 8; j++) acc[j] += zsm[j][k] * w;
    }
    float w2 = W2[tid];
    #pragma unroll
    for (int j = 0; j < 8; j++) {
        float h = fmaxf(acc[j], 0.f) * w2;
        #pragma unroll
        for (int o = 16; o > 0; o >>= 1) h += __shfl_down_sync(0xffffffffu, h, o);
        if ((tid & 31) == 0) red[j][tid >> 5] = h;
    }
    __syncthreads();
    if (tid < 8)
        out[b0 + tid] = red[tid][0] + red[tid][1] + red[tid][2] + red[tid][3] + b2[0];
}

// ---------------- host launcher ---------------------------------------------------
extern "C" void kernel_launch(void* const* d_in, const int* in_sizes, int n_in,
                              void* d_out, int out_size) {
    int ix1 = 0, ie1, ib1, ix2, ie2, ib2;
    if (in_sizes[1] == 2 * N_EDGES) {           // reference-signature order
        ie1 = 1; ib1 = 2; ix2 = 3; ie2 = 4; ib2 = 5;
    } else {                                    // setup_inputs dict order
        ix2 = 1; ie1 = 2; ie2 = 3; ib1 = 4; ib2 = 5;
    }
    const float* x1     = (const float*)d_in[ix1];
    const float* x2     = (const float*)d_in[ix2];
    const int*   e1     = (const int*)d_in[ie1];
    const int*   e2     = (const int*)d_in[ie2];
    const int*   batch1 = (const int*)d_in[ib1];
    const int*   batch2 = (const int*)d_in[ib2];
    const int*   rel    = (const int*)d_in[6];
    const float* Wl     = (const float*)d_in[7];
    const float* bl     = (const float*)d_in[8];
    const float* Wr     = (const float*)d_in[9];
    const float* gam    = (const float*)d_in[10];
    const float* bet    = (const float*)d_in[11];
    const float* mean   = (const float*)d_in[12];
    const float* var    = (const float*)d_in[13];
    const float* kge    = (const float*)d_in[14];
    const float* W1     = (const float*)d_in[15];
    const float* b1     = (const float*)d_in[16];
    const float* W2     = (const float*)d_in[17];
    const float* b2     = (const float*)d_in[18];
    float* out = (float*)d_out;

    static int attr_done = 0;
    if (!attr_done) {
        cudaFuncSetAttribute(gemm_kernel, cudaFuncAttributeMaxDynamicSharedMemorySize,
                             GSMEM);
        attr_done = 1;
    }

    zero_kernel<<<256, 256>>>();
    wsplit_kernel<<<(L_IT * 128 * 256 + 255) / 256, 256>>>(Wl, Wr);

    dim3 gE((N_EDGES + 255) / 256, 2);
    hist_kernel<<<gE, 256>>>(e1, e2);
    scan_kernel<<<2, 1024>>>();
    scatter_kernel<<<gE, 256>>>(e1, e2);

    dim3 gWarp((N_NODES + 7) / 8, 2);
    dim3 gGemm((N_NODES + 127) / 128, 2);

    int in_sel = -1;
    int out_sel = 0;
    for (int l = 0; l < L_IT; l++) {
        agg_kernel<<<gWarp, 256>>>(x1, x2, in_sel);
        gemm_kernel<<<gGemm, 256, GSMEM>>>(x1, x2,
                                           bl + l * DIM,
                                           gam + l * DIM, bet + l * DIM,
                                           mean + l * DIM, var + l * DIM,
                                           l, in_sel, out_sel);
        in_sel = out_sel;
        out_sel ^= 1;
    }

    pool_kernel<<<gWarp, 256>>>(batch1, batch2, in_sel);
    mlp_kernel<<<B_GR / 8, 128>>>(rel, kge, W1, b1, W2, b2, out);
    (void)n_in; (void)out_size;
}